// round 17
// baseline (speedup 1.0000x reference)
#include <cuda_runtime.h>
#include <math.h>

// Problem constants (fixed by setup_inputs)
#define Bc 128
#define Nc 96
#define Dc 3072
#define Kc 10
#define KP 5                         // k-pairs
#define RPW 3                        // rows per warp-unit
#define WARPS 32
#define THREADS (WARPS*32)           // 1024
#define GRID1 128
#define NUNITS (Bc*(Nc/RPW))         // 4096 == GRID1*WARPS, exactly 1 unit/warp
#define ITERS (Dc/64)                // 48 iters; 64 d's per warp-iter (2 per lane)
#define SMEM_BYTES (KP*Dc*8)         // 122880: W as k-pair u64, [kp][d]

typedef unsigned long long u64;

__device__ float g_l1[Bc*Nc];
__device__ float g_l2[Bc*Nc];
__device__ int   g_ticket = 0;

// ---- packed f32x2 ops (Blackwell) ----
#define FMA2(d, a, b, c) \
    asm("fma.rn.f32x2 %0, %1, %2, %3;" : "=l"(d) : "l"(a), "l"(b), "l"(c))
#define ADD2(d, a, b) \
    asm("add.rn.f32x2 %0, %1, %2;" : "=l"(d) : "l"(a), "l"(b))
// scalar saturating add: clip(a+b,0,1) in one FADD.SAT
#define ADDSAT(d, a, b) \
    asm("add.rn.sat.f32 %0, %1, %2;" : "=f"(d) : "f"(a), "f"(b))

__device__ __forceinline__ u64 dup2(float v) {
    u64 r;
    asm("mov.b64 %0, {%1, %1};" : "=l"(r) : "f"(v));
    return r;
}
__device__ __forceinline__ void unpack2(float& lo, float& hi, u64 v) {
    asm("mov.b64 {%0, %1}, %2;" : "=f"(lo), "=f"(hi) : "l"(v));
}

__global__ __launch_bounds__(THREADS, 1)
void logits_kernel(const float* __restrict__ imgs,
                   const float* __restrict__ deltas,
                   const float* __restrict__ Wm,
                   const float* __restrict__ bias,
                   const int*   __restrict__ labels,
                   const int*   __restrict__ indp,
                   float*       __restrict__ out)
{
    extern __shared__ u64 sW2[];   // [KP][Dc]: sW2[kp*Dc+d] = (W[d][2kp], W[d][2kp+1])
    __shared__ float sPart[Bc];
    __shared__ int   sIsLast;

    // W rows are 5 contiguous u64 k-pairs; transpose to kp-major (one-time)
    const u64* Wm64 = (const u64*)Wm;
    for (int idx = threadIdx.x; idx < Dc*KP; idx += THREADS) {
        int d = idx / KP, kp = idx - d*KP;
        sW2[kp*Dc + d] = Wm64[idx];
    }
    __syncthreads();

    const int warp = threadIdx.x >> 5;
    const int lane = threadIdx.x & 31;
    const int u    = blockIdx.x*WARPS + warp;      // 0..4095, exactly one unit
    const int b    = u & (Bc-1);
    const int n0   = (u >> 7) * RPW;

    const float2* img2 = (const float2*)(imgs + (size_t)b*Dc) + lane;
    const float2* dp   = (const float2*)(deltas + ((size_t)n0*Bc + b)*Dc) + lane;
    const ulonglong2* w0 = (const ulonglong2*)sW2 + lane;   // lane's 2-d slice

    u64 acc[RPW*KP];
#pragma unroll
    for (int a = 0; a < RPW*KP; a++) acc[a] = 0ULL;

#pragma unroll 1
    for (int i = 0; i < ITERS; i++) {
        const int e = i*32;                        // float2 index step
        float2 xi  = __ldg(img2 + e);
        float2 dd0 = __ldcs(dp + e);
        float2 dd1 = __ldcs(dp + e + (size_t)Bc*Dc/2);
        float2 dd2 = __ldcs(dp + e + (size_t)Bc*Dc);

        // clip once per (row, d), duplicate into both packed halves
        float a00, a01, a10, a11, a20, a21;
        ADDSAT(a00, xi.x, dd0.x); ADDSAT(a01, xi.y, dd0.y);
        ADDSAT(a10, xi.x, dd1.x); ADDSAT(a11, xi.y, dd1.y);
        ADDSAT(a20, xi.x, dd2.x); ADDSAT(a21, xi.y, dd2.y);
        u64 x00 = dup2(a00), x01 = dup2(a01);
        u64 x10 = dup2(a10), x11 = dup2(a11);
        u64 x20 = dup2(a20), x21 = dup2(a21);

#pragma unroll
        for (int kp = 0; kp < KP; kp++) {
            // (k-pair for d0, k-pair for d1), conflict-free LDS.128
            ulonglong2 w2 = w0[kp*(Dc/2) + e];
            FMA2(acc[0*KP+kp], x00, w2.x, acc[0*KP+kp]);
            FMA2(acc[0*KP+kp], x01, w2.y, acc[0*KP+kp]);
            FMA2(acc[1*KP+kp], x10, w2.x, acc[1*KP+kp]);
            FMA2(acc[1*KP+kp], x11, w2.y, acc[1*KP+kp]);
            FMA2(acc[2*KP+kp], x20, w2.x, acc[2*KP+kp]);
            FMA2(acc[2*KP+kp], x21, w2.y, acc[2*KP+kp]);
        }
    }

    // Epilogue: full packed butterfly per (row, kp), then scalar losses
#pragma unroll
    for (int r = 0; r < RPW; r++) {
        u64 s[KP];
#pragma unroll
        for (int kp = 0; kp < KP; kp++) {
            u64 v = acc[r*KP+kp];
#pragma unroll
            for (int m = 16; m >= 1; m >>= 1) {
                u64 o = __shfl_xor_sync(0xFFFFFFFFu, v, m);
                ADD2(v, v, o);
            }
            s[kp] = v;
        }
        if (lane == 0) {
            float lg[Kc];
#pragma unroll
            for (int kp = 0; kp < KP; kp++) {
                float lo, hi;
                unpack2(lo, hi, s[kp]);
                lg[2*kp]   = lo + __ldg(bias + 2*kp);
                lg[2*kp+1] = hi + __ldg(bias + 2*kp+1);
            }

            // argmax (first occurrence, matches top_k tie rule)
            float m = lg[0]; int t1 = 0;
#pragma unroll
            for (int k = 1; k < Kc; k++)
                if (lg[k] > m) { m = lg[k]; t1 = k; }

            float sum = 0.0f;
#pragma unroll
            for (int k = 0; k < Kc; k++) sum += expf(lg[k] - m);
            float lse = m + logf(sum);

            int lab = __ldg(labels + b);
            float logit_lab = lg[0];
#pragma unroll
            for (int k = 1; k < Kc; k++)
                if (k == lab) logit_lab = lg[k];
            float loss1 = lse - logit_lab;

            float m2 = -INFINITY; int t2 = 0;
#pragma unroll
            for (int k = 0; k < Kc; k++)
                if (k != t1 && lg[k] > m2) { m2 = lg[k]; t2 = k; }
            float logit_t2 = lg[0];
#pragma unroll
            for (int k = 1; k < Kc; k++)
                if (k == t2) logit_t2 = lg[k];

            float loss2 = (t1 == lab) ? (lse - logit_t2) : -10000.0f;

            g_l1[b*Nc + (n0 + r)] = loss1;
            g_l2[b*Nc + (n0 + r)] = loss2;
            __threadfence();   // release this warp's results
        }
    }

    // ---- last-CTA ticket: one CTA runs the selection + final mean ----
    __syncthreads();
    if (threadIdx.x == 0) {
        int t = atomicAdd(&g_ticket, 1);
        sIsLast = (t == GRID1 - 1);
    }
    __syncthreads();
    if (!sIsLast) return;
    __threadfence();   // acquire all CTAs' g_l1/g_l2

    const int ind = __ldg(indp);
    const int rounds = Nc - ind;   // rank ind (stable asc) == rounds-th lex-max of (d, j)

    // warp w handles batches b = 4w .. 4w+3, fully in registers
#pragma unroll 1
    for (int q = 0; q < 4; q++) {
        const int bb = warp*4 + q;
        const float* pl1 = g_l1 + bb*Nc;
        const float* pl2 = g_l2 + bb*Nc;

        float l1a = pl1[lane], l1b = pl1[lane+32], l1c = pl1[lane+64];
        float d0 = l1a - pl2[lane];
        float d1 = l1b - pl2[lane+32];
        float d2 = l1c - pl2[lane+64];

        // per-batch mean of l1
        float ssum = l1a + l1b + l1c;
#pragma unroll
        for (int m = 16; m >= 1; m >>= 1)
            ssum += __shfl_xor_sync(0xFFFFFFFFu, ssum, m);

        // iterative lex-max extraction of (d, j): stable-argsort position ind
        bool a0 = true, a1 = true, a2 = true;
        float sel_l2 = 0.0f;
        for (int r = 0; r < rounds; r++) {
            float bd = -INFINITY; int bj = -1;
            if (a0)                          { bd = d0; bj = lane;      }
            if (a1 && d1 >= bd)              { bd = d1; bj = lane + 32; }  // higher j wins ties
            if (a2 && d2 >= bd)              { bd = d2; bj = lane + 64; }
#pragma unroll
            for (int m = 16; m >= 1; m >>= 1) {
                float od = __shfl_xor_sync(0xFFFFFFFFu, bd, m);
                int   oj = __shfl_xor_sync(0xFFFFFFFFu, bj, m);
                if (od > bd || (od == bd && oj > bj)) { bd = od; bj = oj; }
            }
            if (r == rounds - 1) {
                float v = 0.0f;
                if (bj == lane)           v = l1a - d0;   // l2 = l1 - d
                else if (bj == lane + 32) v = l1b - d1;
                else if (bj == lane + 64) v = l1c - d2;
                sel_l2 = __shfl_sync(0xFFFFFFFFu, v, bj & 31);
            } else {
                if (bj == lane)      a0 = false;
                if (bj == lane + 32) a1 = false;
                if (bj == lane + 64) a2 = false;
            }
        }

        if (lane == 0)
            sPart[bb] = ssum / (float)Nc - sel_l2;
    }

    __syncthreads();
    if (warp == 0) {
        float a = sPart[lane] + sPart[lane+32] + sPart[lane+64] + sPart[lane+96];
#pragma unroll
        for (int m = 16; m >= 1; m >>= 1)
            a += __shfl_xor_sync(0xFFFFFFFFu, a, m);
        if (lane == 0) {
            out[0] = a / (float)Bc;
            g_ticket = 0;             // deterministic state for graph replay
        }
    }
}

extern "C" void kernel_launch(void* const* d_in, const int* in_sizes, int n_in,
                              void* d_out, int out_size)
{
    const float* imgs   = (const float*)d_in[0];
    const float* deltas = (const float*)d_in[1];
    const float* Wm     = (const float*)d_in[2];
    const float* bias   = (const float*)d_in[3];
    const int*   labels = (const int*)d_in[4];
    const int*   indp   = (const int*)d_in[5];
    float* out = (float*)d_out;

    cudaFuncSetAttribute(logits_kernel,
                         cudaFuncAttributeMaxDynamicSharedMemorySize, SMEM_BYTES);

    logits_kernel<<<GRID1, THREADS, SMEM_BYTES>>>(imgs, deltas, Wm, bias,
                                                  labels, indp, out);
}